// round 3
// baseline (speedup 1.0000x reference)
#include <cuda_runtime.h>
#include <cuda_bf16.h>

// Fixed shapes: B=64, P=68, H=W=64  ->  4352 tiles of 4096 pixels
#define HW       4096
#define NTHREADS 256
#define EPS      1e-5f
#define LOG2E    1.4426950408889634f
#define LN2      0.6931471805599453f

typedef unsigned long long u64;

// ---- packed f32x2 helpers (sm_103a packed fp32 pipe; ptxas won't auto-emit) ----
__device__ __forceinline__ u64 pk2(float lo, float hi) {
    u64 r; asm("mov.b64 %0, {%1, %2};" : "=l"(r) : "f"(lo), "f"(hi)); return r;
}
__device__ __forceinline__ float2 up2(u64 v) {
    float2 r; asm("mov.b64 {%0, %1}, %2;" : "=f"(r.x), "=f"(r.y) : "l"(v)); return r;
}
__device__ __forceinline__ u64 fma2(u64 a, u64 b, u64 c) {
    u64 d; asm("fma.rn.f32x2 %0, %1, %2, %3;" : "=l"(d) : "l"(a), "l"(b), "l"(c)); return d;
}
__device__ __forceinline__ u64 add2(u64 a, u64 b) {
    u64 d; asm("add.rn.f32x2 %0, %1, %2;" : "=l"(d) : "l"(a), "l"(b)); return d;
}

__global__ __launch_bounds__(NTHREADS)
void gauss_kl_kernel(const float* __restrict__ hm,
                     const float* __restrict__ means,
                     const float* __restrict__ cov,
                     float* __restrict__ out,
                     float inv_rows)
{
    const int bp  = blockIdx.x;
    const int tid = threadIdx.x;

    // Front-batch the 4 streaming LDG.128 loads for MLP
    const float4* hm4 = reinterpret_cast<const float4*>(hm + (size_t)bp * HW);
    float4 h[4];
#pragma unroll
    for (int k = 0; k < 4; k++) h[k] = __ldcs(&hm4[tid + k * NTHREADS]);

    // Per-tile Gaussian parameters (broadcast, L2-hit)
    const float mx  = means[bp * 2 + 0];
    const float my  = means[bp * 2 + 1];
    const float s00 = cov[bp * 4 + 0];
    const float s01 = cov[bp * 4 + 1];
    const float s10 = cov[bp * 4 + 2];
    const float s11 = cov[bp * 4 + 3];
    const float det = fmaf(s00, s11, -s01 * s10) + EPS;
    const float inv_det = LOG2E / det;           // fold log2(e) in
    // lp2 = log2(e^{-quad/2}) = Ac*dx^2 + Bc*dx*dy + Cc*dy^2
    const float Ac = -0.5f * s11 * inv_det;
    const float Bc =  0.5f * (s01 + s10) * inv_det;
    const float Cc = -0.5f * s00 * inv_det;

    // Geometry: thread owns x in {x0..x0+3}, rows y = yb + {0,16,32,48}
    const float x0f = (float)((tid & 15) << 2);
    const float yb  = (float)(tid >> 4);
    const float xm  = x0f - mx;
    const float dyb = yb - my;
    const u64 dxp01 = pk2(xm,        xm + 1.0f);   // pairs along x (match float4 halves)
    const u64 dxp23 = pk2(xm + 2.0f, xm + 3.0f);
    const u64 A2    = pk2(Ac, Ac);

    // Pass 1: e = exp2(lp2) packed pairwise, S = sum e
    u64 ep[8];
    u64 S2 = 0ull;   // (0.0f, 0.0f)
#pragma unroll
    for (int k = 0; k < 4; k++) {
        const float dy    = dyb + (float)(16 * k);
        const float bdy   = Bc * dy;
        const float cdy2  = (Cc * dy) * dy;
        const u64 bdy2    = pk2(bdy, bdy);
        const u64 cdy22   = pk2(cdy2, cdy2);
        const u64 lpA = fma2(fma2(A2, dxp01, bdy2), dxp01, cdy22);
        const u64 lpB = fma2(fma2(A2, dxp23, bdy2), dxp23, cdy22);
        const float2 la = up2(lpA), lb = up2(lpB);
        const u64 eA = pk2(exp2f(la.x), exp2f(la.y));
        const u64 eB = pk2(exp2f(lb.x), exp2f(lb.y));
        ep[2 * k]     = eA;
        ep[2 * k + 1] = eB;
        S2 = add2(S2, add2(eA, eB));
    }
    const float2 sv = up2(S2);
    float S = sv.x + sv.y;

    // Block reduction of S
    __shared__ float ws[NTHREADS / 32];
    __shared__ float s_bcast;
#pragma unroll
    for (int o = 16; o > 0; o >>= 1) S += __shfl_xor_sync(0xffffffffu, S, o);
    const int wid = tid >> 5, lid = tid & 31;
    if (lid == 0) ws[wid] = S;
    __syncthreads();
    if (tid < (NTHREADS / 32)) {
        float v = ws[tid];
#pragma unroll
        for (int o = (NTHREADS / 64); o > 0; o >>= 1)
            v += __shfl_xor_sync(0xffu, v, o);
        if (tid == 0) s_bcast = v;
    }
    __syncthreads();
    const float Sfull = s_bcast;
    const float c  = EPS * Sfull;               // pr + eps = (e + c)/S
    const u64  c2  = pk2(c, c);
    const u64  N1  = pk2(-1.0f, -1.0f);

    // Pass 2 (registers only):
    //   acc  = sum hm * (lg2(hm) - lg2(e + c)),   hsum = sum hm
    u64 acc2 = 0ull, hs2 = 0ull;
#pragma unroll
    for (int k = 0; k < 4; k++) {
        const u64 h01 = pk2(h[k].x, h[k].y);
        const u64 h23 = pk2(h[k].z, h[k].w);
        {
            const float2 tv = up2(add2(ep[2 * k], c2));
            const u64 lgt = pk2(__log2f(tv.x), __log2f(tv.y));
            const u64 lgh = pk2(__log2f(h[k].x), __log2f(h[k].y));
            const u64 d2  = fma2(lgt, N1, lgh);
            acc2 = fma2(h01, d2, acc2);
            hs2  = add2(hs2, h01);
        }
        {
            const float2 tv = up2(add2(ep[2 * k + 1], c2));
            const u64 lgt = pk2(__log2f(tv.x), __log2f(tv.y));
            const u64 lgh = pk2(__log2f(h[k].z), __log2f(h[k].w));
            const u64 d2  = fma2(lgt, N1, lgh);
            acc2 = fma2(h23, d2, acc2);
            hs2  = add2(hs2, h23);
        }
    }
    const float2 av = up2(acc2);
    const float2 hv = up2(hs2);
    float acc  = av.x + av.y;
    float hsum = hv.x + hv.y;

    // Block reduction of (acc, hsum)
#pragma unroll
    for (int o = 16; o > 0; o >>= 1) {
        acc  += __shfl_xor_sync(0xffffffffu, acc, o);
        hsum += __shfl_xor_sync(0xffffffffu, hsum, o);
    }
    __shared__ float wa[NTHREADS / 32], wh[NTHREADS / 32];
    if (lid == 0) { wa[wid] = acc; wh[wid] = hsum; }
    __syncthreads();
    if (tid < (NTHREADS / 32)) {
        float va = wa[tid], vh = wh[tid];
#pragma unroll
        for (int o = (NTHREADS / 64); o > 0; o >>= 1) {
            va += __shfl_xor_sync(0xffu, va, o);
            vh += __shfl_xor_sync(0xffu, vh, o);
        }
        if (tid == 0) {
            // loss_tile = ln2 * (acc + lg2(S) * hsum)
            const float tile = LN2 * fmaf(__log2f(Sfull), vh, va);
            atomicAdd(out, tile * inv_rows);
        }
    }
}

extern "C" void kernel_launch(void* const* d_in, const int* in_sizes, int n_in,
                              void* d_out, int out_size)
{
    const float* hm    = (const float*)d_in[0];   // [B,P,H,W]
    const float* means = (const float*)d_in[1];   // [B,P,2]
    const float* cov   = (const float*)d_in[2];   // [B,P,4]
    float* out = (float*)d_out;

    const int n_bp = in_sizes[1] / 2;             // 4352

    cudaMemsetAsync(out, 0, (size_t)out_size * sizeof(float));
    gauss_kl_kernel<<<n_bp, NTHREADS>>>(hm, means, cov, out, 1.0f / (float)n_bp);
}

// round 4
// speedup vs baseline: 1.0142x; 1.0142x over previous
#include <cuda_runtime.h>
#include <cuda_bf16.h>

// Fixed shapes: B=64, P=68, H=W=64  ->  4352 tiles of 4096 pixels
#define HW       4096
#define NTHREADS 256
#define EPS      1e-5f
#define LOG2E    1.4426950408889634f
#define LN2      0.6931471805599453f

typedef unsigned long long u64;

// ---- fast MUFU intrinsics (exp2f is PRECISE libm without fast-math!) ----
__device__ __forceinline__ float ex2(float x) {
    float r; asm("ex2.approx.ftz.f32 %0, %1;" : "=f"(r) : "f"(x)); return r;
}
__device__ __forceinline__ float lg2(float x) {
    float r; asm("lg2.approx.f32 %0, %1;" : "=f"(r) : "f"(x)); return r;
}

// ---- packed f32x2 helpers (sm_103a packed fp32 pipe) ----
__device__ __forceinline__ u64 pk2(float lo, float hi) {
    u64 r; asm("mov.b64 %0, {%1, %2};" : "=l"(r) : "f"(lo), "f"(hi)); return r;
}
__device__ __forceinline__ float2 up2(u64 v) {
    float2 r; asm("mov.b64 {%0, %1}, %2;" : "=f"(r.x), "=f"(r.y) : "l"(v)); return r;
}
__device__ __forceinline__ u64 fma2(u64 a, u64 b, u64 c) {
    u64 d; asm("fma.rn.f32x2 %0, %1, %2, %3;" : "=l"(d) : "l"(a), "l"(b), "l"(c)); return d;
}
__device__ __forceinline__ u64 add2(u64 a, u64 b) {
    u64 d; asm("add.rn.f32x2 %0, %1, %2;" : "=l"(d) : "l"(a), "l"(b)); return d;
}

__global__ __launch_bounds__(NTHREADS)
void gauss_kl_kernel(const float* __restrict__ hm,
                     const float* __restrict__ means,
                     const float* __restrict__ cov,
                     float* __restrict__ out,
                     float inv_rows)
{
    const int bp  = blockIdx.x;
    const int tid = threadIdx.x;

    // Front-batch the 4 streaming LDG.128 loads for MLP
    const float4* hm4 = reinterpret_cast<const float4*>(hm + (size_t)bp * HW);
    float4 h[4];
#pragma unroll
    for (int k = 0; k < 4; k++) h[k] = __ldcs(&hm4[tid + k * NTHREADS]);

    // Per-tile Gaussian parameters (broadcast, L2-hit)
    const float mx  = means[bp * 2 + 0];
    const float my  = means[bp * 2 + 1];
    const float s00 = cov[bp * 4 + 0];
    const float s01 = cov[bp * 4 + 1];
    const float s10 = cov[bp * 4 + 2];
    const float s11 = cov[bp * 4 + 3];
    const float det = fmaf(s00, s11, -s01 * s10) + EPS;
    const float inv_det = LOG2E / det;           // fold log2(e) in
    // lp2 = log2(e^{-quad/2}) = Ac*dx^2 + Bc*dx*dy + Cc*dy^2
    const float Ac = -0.5f * s11 * inv_det;
    const float Bc =  0.5f * (s01 + s10) * inv_det;
    const float Cc = -0.5f * s00 * inv_det;

    // Geometry: thread owns x in {x0..x0+3}, rows y = yb + {0,16,32,48}
    const float x0f = (float)((tid & 15) << 2);
    const float yb  = (float)(tid >> 4);
    const float xm  = x0f - mx;
    const float dyb = yb - my;
    const u64 dxp01 = pk2(xm,        xm + 1.0f);
    const u64 dxp23 = pk2(xm + 2.0f, xm + 3.0f);
    const u64 A2    = pk2(Ac, Ac);

    // Pass 1: e = 2^lp2 (raw EX2), S = sum e
    float e[16];
    u64 S2 = 0ull;
#pragma unroll
    for (int k = 0; k < 4; k++) {
        const float dy    = dyb + (float)(16 * k);
        const float bdy   = Bc * dy;
        const float cdy2  = (Cc * dy) * dy;
        const u64 bdy2    = pk2(bdy, bdy);
        const u64 cdy22   = pk2(cdy2, cdy2);
        const u64 lpA = fma2(fma2(A2, dxp01, bdy2), dxp01, cdy22);
        const u64 lpB = fma2(fma2(A2, dxp23, bdy2), dxp23, cdy22);
        const float2 la = up2(lpA), lb = up2(lpB);
        const float e0 = ex2(la.x), e1 = ex2(la.y);
        const float e2 = ex2(lb.x), e3 = ex2(lb.y);
        e[4 * k + 0] = e0; e[4 * k + 1] = e1;
        e[4 * k + 2] = e2; e[4 * k + 3] = e3;
        S2 = add2(S2, add2(pk2(e0, e1), pk2(e2, e3)));
    }
    const float2 sv = up2(S2);
    float S = sv.x + sv.y;

    // Block reduction of S
    __shared__ float ws[NTHREADS / 32];
    __shared__ float s_bcast;
#pragma unroll
    for (int o = 16; o > 0; o >>= 1) S += __shfl_xor_sync(0xffffffffu, S, o);
    const int wid = tid >> 5, lid = tid & 31;
    if (lid == 0) ws[wid] = S;
    __syncthreads();
    if (tid < (NTHREADS / 32)) {
        float v = ws[tid];
#pragma unroll
        for (int o = (NTHREADS / 64); o > 0; o >>= 1)
            v += __shfl_xor_sync(0xffu, v, o);
        if (tid == 0) s_bcast = v;
    }
    __syncthreads();
    const float Sfull = s_bcast;
    const float c  = EPS * Sfull;               // pr + eps = (e + c)/S
    const u64  c2  = pk2(c, c);
    const u64  N1  = pk2(-1.0f, -1.0f);

    // Pass 2 (registers only):
    //   acc = sum hm * (lg2(hm) - lg2(e + c)),   hsum = sum hm
    u64 acc2 = 0ull, hs2 = 0ull;
#pragma unroll
    for (int k = 0; k < 4; k++) {
        const u64 h01 = pk2(h[k].x, h[k].y);
        const u64 h23 = pk2(h[k].z, h[k].w);
        {
            const float2 tv = up2(add2(pk2(e[4*k], e[4*k+1]), c2));
            const u64 lgt = pk2(lg2(tv.x), lg2(tv.y));
            const u64 lgh = pk2(lg2(h[k].x), lg2(h[k].y));
            const u64 d2  = fma2(lgt, N1, lgh);
            acc2 = fma2(h01, d2, acc2);
            hs2  = add2(hs2, h01);
        }
        {
            const float2 tv = up2(add2(pk2(e[4*k+2], e[4*k+3]), c2));
            const u64 lgt = pk2(lg2(tv.x), lg2(tv.y));
            const u64 lgh = pk2(lg2(h[k].z), lg2(h[k].w));
            const u64 d2  = fma2(lgt, N1, lgh);
            acc2 = fma2(h23, d2, acc2);
            hs2  = add2(hs2, h23);
        }
    }
    const float2 av = up2(acc2);
    const float2 hv = up2(hs2);
    float acc  = av.x + av.y;
    float hsum = hv.x + hv.y;

    // Block reduction of (acc, hsum)
#pragma unroll
    for (int o = 16; o > 0; o >>= 1) {
        acc  += __shfl_xor_sync(0xffffffffu, acc, o);
        hsum += __shfl_xor_sync(0xffffffffu, hsum, o);
    }
    __shared__ float wa[NTHREADS / 32], wh[NTHREADS / 32];
    if (lid == 0) { wa[wid] = acc; wh[wid] = hsum; }
    __syncthreads();
    if (tid < (NTHREADS / 32)) {
        float va = wa[tid], vh = wh[tid];
#pragma unroll
        for (int o = (NTHREADS / 64); o > 0; o >>= 1) {
            va += __shfl_xor_sync(0xffu, va, o);
            vh += __shfl_xor_sync(0xffu, vh, o);
        }
        if (tid == 0) {
            // loss_tile = ln2 * (acc + lg2(S) * hsum)
            const float tile = LN2 * fmaf(lg2(Sfull), vh, va);
            atomicAdd(out, tile * inv_rows);
        }
    }
}

extern "C" void kernel_launch(void* const* d_in, const int* in_sizes, int n_in,
                              void* d_out, int out_size)
{
    const float* hm    = (const float*)d_in[0];   // [B,P,H,W]
    const float* means = (const float*)d_in[1];   // [B,P,2]
    const float* cov   = (const float*)d_in[2];   // [B,P,4]
    float* out = (float*)d_out;

    const int n_bp = in_sizes[1] / 2;             // 4352

    cudaMemsetAsync(out, 0, (size_t)out_size * sizeof(float));
    gauss_kl_kernel<<<n_bp, NTHREADS>>>(hm, means, cov, out, 1.0f / (float)n_bp);
}